// round 17
// baseline (speedup 1.0000x reference)
#include <cuda_runtime.h>
#include <cstdint>
#include <cuda_fp16.h>
#include <math_constants.h>
#include <mma.h>

using namespace nvcuda;

#define B_  4
#define T_  4096
#define D_  1024
#define N_  2048
#define L_  768
#define H_  16
#define DH  64
#define NSEG 8
#define STAGES 3

// ---------------- scratch (static device globals; no allocation) ----------------
__device__ __half g_nx1[(size_t)B_ * T_ * D_];
__device__ __half g_nx2[(size_t)B_ * N_ * L_];
__device__ float  g_q  [(size_t)B_ * T_ * D_];
__device__ float  g_k  [(size_t)B_ * N_ * D_];
__device__ float  g_v  [(size_t)B_ * N_ * D_];
__device__ float  g_ap [(size_t)NSEG * B_ * H_ * DH * DH];
__device__ float  g_attn[(size_t)B_ * H_ * DH * DH];
__device__ __half g_wq[(size_t)D_ * D_];
__device__ __half g_wk[(size_t)L_ * D_];
__device__ __half g_wv[(size_t)L_ * D_];
__device__ __half g_wh[(size_t)D_ * D_];
__device__ __half g_x1h[(size_t)B_ * T_ * D_];

// ---------------- helpers ----------------
__device__ __forceinline__ void cp16(__half* smem_dst, const __half* gsrc) {
    unsigned int s = (unsigned int)__cvta_generic_to_shared(smem_dst);
    asm volatile("cp.async.cg.shared.global [%0], [%1], 16;" :: "r"(s), "l"(gsrc));
}
__device__ __forceinline__ void cp_commit() { asm volatile("cp.async.commit_group;" ::); }
__device__ __forceinline__ void cp_wait1()  { asm volatile("cp.async.wait_group 1;" ::); }

// ---------------- float -> half conversion copy ----------------
__global__ void __launch_bounds__(256) tohalf_kernel(const float* __restrict__ src,
                                                     __half* __restrict__ dst) {
    size_t i = ((size_t)blockIdx.x * 256 + threadIdx.x) * 4;
    float4 t = *(const float4*)(src + i);
    __half2 lo = __floats2half2_rn(t.x, t.y);
    __half2 hi = __floats2half2_rn(t.z, t.w);
    *(__half2*)(dst + i)     = lo;
    *(__half2*)(dst + i + 2) = hi;
}

// ---------------- LayerNorm (emits half output) ----------------
__global__ void __launch_bounds__(256) ln_kernel(const float* __restrict__ x,
                                                 const float* __restrict__ g,
                                                 const float* __restrict__ bb,
                                                 __half* __restrict__ out, int D) {
    int row = blockIdx.x;
    const float* xr = x + (size_t)row * D;
    int cnt = D >> 8;
    float v[4];
    float s = 0.f, s2 = 0.f;
    for (int i = 0; i < cnt; i++) {
        v[i] = xr[threadIdx.x + (i << 8)];
        s += v[i];
        s2 += v[i] * v[i];
    }
    #pragma unroll
    for (int o = 16; o; o >>= 1) {
        s  += __shfl_xor_sync(0xffffffffu, s, o);
        s2 += __shfl_xor_sync(0xffffffffu, s2, o);
    }
    __shared__ float sa[8], sb[8];
    int w = threadIdx.x >> 5, lane = threadIdx.x & 31;
    if (lane == 0) { sa[w] = s; sb[w] = s2; }
    __syncthreads();
    if (w == 0) {
        s  = (lane < 8) ? sa[lane] : 0.f;
        s2 = (lane < 8) ? sb[lane] : 0.f;
        #pragma unroll
        for (int o = 4; o; o >>= 1) {
            s  += __shfl_xor_sync(0xffffffffu, s, o);
            s2 += __shfl_xor_sync(0xffffffffu, s2, o);
        }
        if (lane == 0) { sa[0] = s; sb[0] = s2; }
    }
    __syncthreads();
    float invD = 1.f / (float)D;
    float mu  = sa[0] * invD;
    float var = sb[0] * invD - mu * mu;
    float inv = rsqrtf(var + 1e-5f);
    __half* orow = out + (size_t)row * D;
    for (int i = 0; i < cnt; i++) {
        int c = threadIdx.x + (i << 8);
        orow[c] = __float2half_rn((v[i] - mu) * inv * g[c] + bb[c]);
    }
}

// ---------------- GEMM: C[M,N](f32) = A[M,K](f16) @ W[K,N](f16), fp16 wmma ----------------
// BM=128 BN=128 BK=32, 256 threads (8 warps in 2x4), warp tile 64x32, wmma 16x16x16.
// 3-stage cp.async ring: 56832B. Epilogue float tile (modes 1/2): 128x132x4 = 67584B.
// Dyn smem = 67584B -> 2 CTAs/SM (135KB), regs capped via launch_bounds.
// MODE 0: plain store.  MODE 1: +bias.  MODE 2: +bias then softmax over each 64-col head chunk.
#define A_PITCH 40
#define B_PITCH 136
#define STG_HALVES 9472    // 128*40 + 32*136
#define EPI_PITCH 132
#define GSM_BYTES 67584    // max(3*9472*2, 128*132*4)

template<int MODE>
__global__ void __launch_bounds__(256, 2) gemm_f16_ep(const __half* __restrict__ A,
                                                      const __half* __restrict__ W,
                                                      float* __restrict__ C,
                                                      const float* __restrict__ bias,
                                                      int M, int N, int K) {
    extern __shared__ __half sm[];
    int bm = blockIdx.y * 128, bn = blockIdx.x * 128;
    int tid = threadIdx.x;
    int wid = tid >> 5;
    int wm = (wid >> 2) * 64, wn = (wid & 3) * 32;

    wmma::fragment<wmma::accumulator, 16, 16, 16, float> acc[4][2];
    #pragma unroll
    for (int i = 0; i < 4; i++)
        #pragma unroll
        for (int j = 0; j < 2; j++) wmma::fill_fragment(acc[i][j], 0.f);

    int KT = K >> 5;

    // prologue
    #pragma unroll
    for (int s = 0; s < STAGES - 1; s++) {
        __half* as = sm + s * STG_HALVES;
        __half* bs = as + 128 * A_PITCH;
        int k0 = s << 5;
        #pragma unroll
        for (int i = 0; i < 2; i++) {
            int idx = tid + i * 256;
            int r = idx >> 2, c = (idx & 3) << 3;
            cp16(as + r * A_PITCH + c, A + (size_t)(bm + r) * K + k0 + c);
        }
        #pragma unroll
        for (int i = 0; i < 2; i++) {
            int idx = tid + i * 256;
            int r = idx >> 4, c = (idx & 15) << 3;
            cp16(bs + r * B_PITCH + c, W + (size_t)(k0 + r) * N + bn + c);
        }
        cp_commit();
    }

    for (int kt = 0; kt < KT; kt++) {
        cp_wait1();
        __syncthreads();

        int ldk = kt + STAGES - 1;
        if (ldk < KT) {
            int s = ldk % STAGES;
            __half* as = sm + s * STG_HALVES;
            __half* bs = as + 128 * A_PITCH;
            int k0 = ldk << 5;
            #pragma unroll
            for (int i = 0; i < 2; i++) {
                int idx = tid + i * 256;
                int r = idx >> 2, c = (idx & 3) << 3;
                cp16(as + r * A_PITCH + c, A + (size_t)(bm + r) * K + k0 + c);
            }
            #pragma unroll
            for (int i = 0; i < 2; i++) {
                int idx = tid + i * 256;
                int r = idx >> 4, c = (idx & 15) << 3;
                cp16(bs + r * B_PITCH + c, W + (size_t)(k0 + r) * N + bn + c);
            }
        }
        cp_commit();

        int s = kt % STAGES;
        __half* as = sm + s * STG_HALVES;
        __half* bs = as + 128 * A_PITCH;
        #pragma unroll
        for (int kk = 0; kk < 32; kk += 16) {
            wmma::fragment<wmma::matrix_a, 16, 16, 16, __half, wmma::row_major> af[4];
            wmma::fragment<wmma::matrix_b, 16, 16, 16, __half, wmma::row_major> bf[2];
            #pragma unroll
            for (int i = 0; i < 4; i++)
                wmma::load_matrix_sync(af[i], as + (wm + 16 * i) * A_PITCH + kk, A_PITCH);
            #pragma unroll
            for (int j = 0; j < 2; j++)
                wmma::load_matrix_sync(bf[j], bs + kk * B_PITCH + wn + 16 * j, B_PITCH);
            #pragma unroll
            for (int i = 0; i < 4; i++)
                #pragma unroll
                for (int j = 0; j < 2; j++)
                    wmma::mma_sync(acc[i][j], af[i], bf[j], acc[i][j]);
        }
        __syncthreads();
    }

    if (MODE == 0) {
        #pragma unroll
        for (int i = 0; i < 4; i++)
            #pragma unroll
            for (int j = 0; j < 2; j++)
                wmma::store_matrix_sync(C + (size_t)(bm + wm + 16 * i) * N + bn + wn + 16 * j,
                                        acc[i][j], N, wmma::mem_row_major);
        return;
    }

    // fused epilogue: stage tile through smem (float, pitch 132)
    float* sf = reinterpret_cast<float*>(sm);
    #pragma unroll
    for (int i = 0; i < 4; i++)
        #pragma unroll
        for (int j = 0; j < 2; j++)
            wmma::store_matrix_sync(sf + (wm + 16 * i) * EPI_PITCH + wn + 16 * j,
                                    acc[i][j], EPI_PITCH, wmma::mem_row_major);
    __syncthreads();

    int row = tid >> 1, ch = tid & 1;                 // 128 rows x 2 head-chunks
    const float* srow = sf + row * EPI_PITCH + ch * 64;
    const float* brow = bias + bn + ch * 64;
    float* orow = C + (size_t)(bm + row) * N + bn + ch * 64;

    if (MODE == 1) {
        #pragma unroll 8
        for (int c = 0; c < 64; c++)
            orow[c] = srow[c] + brow[c];
    } else {
        // online softmax over the 64-col head chunk (bias added pre-softmax)
        float m = -CUDART_INF_F, s = 0.f;
        #pragma unroll 8
        for (int c = 0; c < 64; c++) {
            float v = srow[c] + brow[c];
            float nm = fmaxf(m, v);
            s = s * __expf(m - nm) + __expf(v - nm);
            m = nm;
        }
        float inv = 1.f / s;
        #pragma unroll 8
        for (int c = 0; c < 64; c++)
            orow[c] = __expf(srow[c] + brow[c] - m) * inv;
    }
}

// ---------------- attn partials ----------------
__global__ void __launch_bounds__(256) attn_part_kernel(const float* __restrict__ k,
                                                        const float* __restrict__ v,
                                                        float* __restrict__ ap) {
    __shared__ float ks[32][68], vs[32][68];
    int bh = blockIdx.x;
    int b = bh >> 4, h = bh & 15;
    int seg = blockIdx.y;
    int tid = threadIdx.x;
    int d0 = (tid >> 4) << 2, l0 = (tid & 15) << 2;
    float acc[4][4];
    #pragma unroll
    for (int i = 0; i < 4; i++)
        #pragma unroll
        for (int j = 0; j < 4; j++) acc[i][j] = 0.f;

    const float* kb = k + (size_t)(b * N_) * D_ + h * 64;
    const float* vb = v + (size_t)(b * N_) * D_ + h * 64;
    int nend = seg * 256 + 256;
    for (int n0 = seg * 256; n0 < nend; n0 += 32) {
        #pragma unroll
        for (int i = 0; i < 2; i++) {
            int idx = tid + i * 256;
            int r = idx >> 4, c = (idx & 15) << 2;
            *(float4*)&ks[r][c] = *(const float4*)(kb + (size_t)(n0 + r) * D_ + c);
            *(float4*)&vs[r][c] = *(const float4*)(vb + (size_t)(n0 + r) * D_ + c);
        }
        __syncthreads();
        #pragma unroll 8
        for (int n = 0; n < 32; n++) {
            float kr[4], vr[4];
            #pragma unroll
            for (int i = 0; i < 4; i++) { kr[i] = ks[n][d0 + i]; vr[i] = vs[n][l0 + i]; }
            #pragma unroll
            for (int i = 0; i < 4; i++)
                #pragma unroll
                for (int j = 0; j < 4; j++) acc[i][j] += kr[i] * vr[j];
        }
        __syncthreads();
    }
    float* dst = ap + ((size_t)seg * (B_ * H_) + bh) * 4096;
    #pragma unroll
    for (int i = 0; i < 4; i++)
        #pragma unroll
        for (int j = 0; j < 4; j++) dst[(d0 + i) * 64 + l0 + j] = acc[i][j];
}

__global__ void __launch_bounds__(256) attn_reduce_kernel(const float* __restrict__ ap,
                                                          float* __restrict__ attn) {
    int i = blockIdx.x * blockDim.x + threadIdx.x;
    #pragma unroll
    for (int r = 0; r < 4; r++) {
        int j = i + r * 65536;
        float s = 0.f;
        #pragma unroll
        for (int sg = 0; sg < NSEG; sg++) s += ap[(size_t)sg * (B_ * H_ * 4096) + j];
        attn[j] = s;
    }
}

// ---------------- final: out = Ch + bh + q @ attn ----------------
__global__ void __launch_bounds__(256) final_kernel(const float* __restrict__ Ch,
                                                    const float* __restrict__ bh,
                                                    const float* __restrict__ q,
                                                    const float* __restrict__ attn,
                                                    float* __restrict__ out) {
    __shared__ float sA[64][64];
    __shared__ float sQ[64][68];
    int t0 = blockIdx.x * 64, h = blockIdx.y, b = blockIdx.z;
    int tid = threadIdx.x;
    const float* ap = attn + (size_t)(b * H_ + h) * 4096;
    #pragma unroll
    for (int i = 0; i < 4; i++) {
        int idx = tid + i * 256;
        int r = idx >> 4, c = (idx & 15) << 2;
        *(float4*)&sA[r][c] = *(const float4*)(ap + r * 64 + c);
    }
    #pragma unroll
    for (int i = 0; i < 4; i++) {
        int idx = tid + i * 256;
        int r = idx >> 4, c = (idx & 15) << 2;
        *(float4*)&sQ[r][c] = *(const float4*)(q + (size_t)(b * T_ + t0 + r) * D_ + h * 64 + c);
    }
    __syncthreads();
    int tl = tid >> 2, l0 = (tid & 3) << 4;
    float accv[16];
    #pragma unroll
    for (int j = 0; j < 16; j++) accv[j] = 0.f;
    #pragma unroll 4
    for (int d = 0; d < 64; d++) {
        float qd = sQ[tl][d];
        #pragma unroll
        for (int jj = 0; jj < 4; jj++) {
            float4 a4 = *(const float4*)&sA[d][l0 + jj * 4];
            accv[jj * 4 + 0] += qd * a4.x;
            accv[jj * 4 + 1] += qd * a4.y;
            accv[jj * 4 + 2] += qd * a4.z;
            accv[jj * 4 + 3] += qd * a4.w;
        }
    }
    size_t base = (size_t)(b * T_ + t0 + tl) * D_ + h * 64 + l0;
    #pragma unroll
    for (int j = 0; j < 16; j++)
        out[base + j] = Ch[base + j] + bh[h * 64 + l0 + j] + accv[j];
}

// ---------------- launch ----------------
extern "C" void kernel_launch(void* const* d_in, const int* in_sizes, int n_in,
                              void* d_out, int out_size) {
    const float* x1 = (const float*)d_in[0];
    const float* x2 = (const float*)d_in[1];
    const float* Wq = (const float*)d_in[2];
    const float* bq = (const float*)d_in[3];
    const float* Wk = (const float*)d_in[4];
    const float* bk = (const float*)d_in[5];
    const float* Wv = (const float*)d_in[6];
    const float* bv = (const float*)d_in[7];
    const float* Wh = (const float*)d_in[8];
    const float* bh = (const float*)d_in[9];
    const float* g1 = (const float*)d_in[10];
    const float* b1 = (const float*)d_in[11];
    const float* g2 = (const float*)d_in[12];
    const float* b2 = (const float*)d_in[13];
    float* out = (float*)d_out;

    __half *nx1, *nx2, *wq, *wk, *wv, *wh, *x1h;
    float *q, *k, *v, *ap, *attn;
    cudaGetSymbolAddress((void**)&nx1, g_nx1);
    cudaGetSymbolAddress((void**)&nx2, g_nx2);
    cudaGetSymbolAddress((void**)&q,   g_q);
    cudaGetSymbolAddress((void**)&k,   g_k);
    cudaGetSymbolAddress((void**)&v,   g_v);
    cudaGetSymbolAddress((void**)&ap,  g_ap);
    cudaGetSymbolAddress((void**)&attn, g_attn);
    cudaGetSymbolAddress((void**)&wq,  g_wq);
    cudaGetSymbolAddress((void**)&wk,  g_wk);
    cudaGetSymbolAddress((void**)&wv,  g_wv);
    cudaGetSymbolAddress((void**)&wh,  g_wh);
    cudaGetSymbolAddress((void**)&x1h, g_x1h);

    static bool attr_set = false;
    if (!attr_set) {
        cudaFuncSetAttribute(gemm_f16_ep<0>, cudaFuncAttributeMaxDynamicSharedMemorySize, GSM_BYTES);
        cudaFuncSetAttribute(gemm_f16_ep<1>, cudaFuncAttributeMaxDynamicSharedMemorySize, GSM_BYTES);
        cudaFuncSetAttribute(gemm_f16_ep<2>, cudaFuncAttributeMaxDynamicSharedMemorySize, GSM_BYTES);
        attr_set = true;
    }

    // half conversions (weights + x1)
    tohalf_kernel<<<(D_ * D_) / 1024, 256>>>(Wq, wq);
    tohalf_kernel<<<(L_ * D_) / 1024, 256>>>(Wk, wk);
    tohalf_kernel<<<(L_ * D_) / 1024, 256>>>(Wv, wv);
    tohalf_kernel<<<(D_ * D_) / 1024, 256>>>(Wh, wh);
    tohalf_kernel<<<(B_ * T_ * D_) / 1024, 256>>>(x1, x1h);

    // LayerNorms (half outputs)
    ln_kernel<<<B_ * T_, 256>>>(x1, g1, b1, nx1, D_);
    ln_kernel<<<B_ * N_, 256>>>(x2, g2, b2, nx2, L_);

    // Q = softmax(nx1 @ Wq + bq) per head  (fused epilogue)
    gemm_f16_ep<2><<<dim3(D_ / 128, (B_ * T_) / 128), 256, GSM_BYTES>>>(nx1, wq, q, bq, B_ * T_, D_, D_);

    // K = softmax(nx2 @ Wk + bk) per head  (fused epilogue)
    gemm_f16_ep<2><<<dim3(D_ / 128, (B_ * N_) / 128), 256, GSM_BYTES>>>(nx2, wk, k, bk, B_ * N_, D_, L_);

    // V = nx2 @ Wv + bv  (fused bias)
    gemm_f16_ep<1><<<dim3(D_ / 128, (B_ * N_) / 128), 256, GSM_BYTES>>>(nx2, wv, v, bv, B_ * N_, D_, L_);

    // attn = k^T v per (b,h): split-N partials then deterministic reduce
    attn_part_kernel<<<dim3(B_ * H_, NSEG), 256>>>(k, v, ap);
    attn_reduce_kernel<<<256, 256>>>(ap, attn);

    // out = x1 @ Wh, then += bh + q @ attn
    gemm_f16_ep<0><<<dim3(D_ / 128, (B_ * T_) / 128), 256, GSM_BYTES>>>(x1h, wh, out, nullptr, B_ * T_, D_, D_);
    final_kernel<<<dim3(T_ / 64, H_, B_), 256>>>(out, bh, q, attn, out);
}